// round 3
// baseline (speedup 1.0000x reference)
#include <cuda_runtime.h>
#include <math.h>

// Problem constants
#define NB   64     // batch
#define LSEQ 512    // seq len
#define NE   64     // enc_in
#define NPRED 512
#define KTOP 20
#define NFREQ 257   // rfft bins
#define NSPEC 576   // padded 2*257=514 -> 576 (9 tiles of 64)

// ---------------- scratch (static device memory; no allocations) ----------------
__device__ __align__(16) float g_dftW[NSPEC * LSEQ];          // DFT matrix [576][512] (rows: 2f=cos, 2f+1=-sin; >=514 zero)
__device__ __align__(16) float g_tw[LSEQ * 2];                // twiddle table cos/sin(2*pi*j/512)
__device__ __align__(16) float g_spec[NB * NE * NSPEC];       // [4096][576]
__device__ __align__(16) float g_xfilt[NB * LSEQ * NE];
__device__ __align__(16) float g_norm [NB * LSEQ * NE];
__device__ __align__(16) float g_q[NB * LSEQ * NE];
__device__ __align__(16) float g_k[NB * LSEQ * NE];
__device__ __align__(16) float g_v[NB * LSEQ * NE];
__device__ __align__(16) float g_h[NB * NE * 1024];           // [4096][1024] MLP input
__device__ __align__(16) float g_hidden[NB * NE * 3072];      // [4096][3072]

// ---------------- setup: DFT matrix + twiddle table ----------------
__global__ void setup_kernel() {
    int i = blockIdx.x * blockDim.x + threadIdx.x;
    const float w0 = 6.283185307179586f / 512.0f;
    if (i < NSPEC * LSEQ) {
        int n = i / LSEQ, t = i % LSEQ;
        float v = 0.0f;
        if (n < 2 * NFREQ) {
            int f = n >> 1;
            int j = (f * t) & 511;          // exact angle reduction
            float ang = (float)j * w0;
            v = (n & 1) ? -sinf(ang) : cosf(ang);
        }
        g_dftW[i] = v;
    } else if (i < NSPEC * LSEQ + LSEQ) {
        int j = i - NSPEC * LSEQ;
        float ang = (float)j * w0;
        float s, c; sincosf(ang, &s, &c);
        g_tw[2 * j] = c; g_tw[2 * j + 1] = s;
    }
}

// ---------------- generic register-tiled SGEMM: C = A @ B^T (+bias, epilogue) ----------------
// AMODE 0: A row-major [M][K]
// AMODE 1: A is [b][t][c] tensor viewed as [m=b*64+c][k=t]  (requires BM=64, M%64==0)
// EPI 0: plain (+optional bias) -> C[m*N+n]
// EPI 1: relu(+bias)            -> C[m*N+n]
// EPI 2: FAN layer: n<128 -> p (write gt*cos to h[n], gt*sin to h[128+n]); n>=128 -> gelu from B2/bias2 -> h[n+128]; C=h ld 1024
// EPI 3: fc2 scatter-transpose: C[((m>>6)*512 + n)*64 + (m&63)]
template<int BM, int BN, int BK, int TM, int TN, int AMODE, int EPI>
__global__ __launch_bounds__(256) void sgemm_kernel(
    const float* __restrict__ A, const float* __restrict__ B,
    const float* __restrict__ B2, const float* __restrict__ bias,
    const float* __restrict__ bias2, float* __restrict__ C,
    int M, int N, int K, const float* __restrict__ gate)
{
    constexpr int LDA = BM + 4;
    constexpr int LDB = BN + 4;
    static_assert((BM / TM) * (BN / TN) == 256, "thread count");
    __shared__ __align__(16) float As[BK * LDA];
    __shared__ __align__(16) float Bs[BK * LDB];

    const int tid  = threadIdx.x;
    const int m0   = blockIdx.y * BM;
    const int n0   = blockIdx.x * BN;
    const int tcol = tid & ((BN / TN) - 1);      // BN/TN == 16 for all configs
    const int trow = tid / (BN / TN);

    float acc[TM][TN];
#pragma unroll
    for (int i = 0; i < TM; i++)
#pragma unroll
        for (int j = 0; j < TN; j++) acc[i][j] = 0.0f;

    for (int k0 = 0; k0 < K; k0 += BK) {
        // ---- load A tile (transposed into smem: As[k][m]) ----
        if constexpr (AMODE == 0) {
#pragma unroll
            for (int i = tid * 4; i < BM * BK; i += 1024) {
                int row = i / BK, col = i % BK;
                float4 va = *reinterpret_cast<const float4*>(&A[(size_t)(m0 + row) * K + k0 + col]);
                As[(col + 0) * LDA + row] = va.x;
                As[(col + 1) * LDA + row] = va.y;
                As[(col + 2) * LDA + row] = va.z;
                As[(col + 3) * LDA + row] = va.w;
            }
        } else {
#pragma unroll
            for (int i = tid; i < BM * BK; i += 256) {
                int row = i & (BM - 1);
                int col = i / BM;
                int gm = m0 + row;
                As[col * LDA + row] = A[((size_t)(gm >> 6) * K + (k0 + col)) * 64 + (gm & 63)];
            }
        }
        // ---- load B tile (Bs[k][n]) ----
#pragma unroll
        for (int i = tid * 4; i < BN * BK; i += 1024) {
            int row = i / BK, col = i % BK;
            int gn = n0 + row;
            const float* Bp;
            if constexpr (EPI == 2) Bp = (gn < 128) ? (B + (size_t)gn * K) : (B2 + (size_t)(gn - 128) * K);
            else                    Bp = B + (size_t)gn * K;
            float4 vb = *reinterpret_cast<const float4*>(&Bp[k0 + col]);
            Bs[(col + 0) * LDB + row] = vb.x;
            Bs[(col + 1) * LDB + row] = vb.y;
            Bs[(col + 2) * LDB + row] = vb.z;
            Bs[(col + 3) * LDB + row] = vb.w;
        }
        __syncthreads();
#pragma unroll
        for (int k = 0; k < BK; k++) {
            float a[TM], bv[TN];
#pragma unroll
            for (int i = 0; i < TM; i += 4)
                *reinterpret_cast<float4*>(&a[i]) =
                    *reinterpret_cast<const float4*>(&As[k * LDA + trow * TM + i]);
#pragma unroll
            for (int j = 0; j < TN; j += 4)
                *reinterpret_cast<float4*>(&bv[j]) =
                    *reinterpret_cast<const float4*>(&Bs[k * LDB + tcol * TN + j]);
#pragma unroll
            for (int i = 0; i < TM; i++)
#pragma unroll
                for (int j = 0; j < TN; j++)
                    acc[i][j] = fmaf(a[i], bv[j], acc[i][j]);
        }
        __syncthreads();
    }

    // ---- epilogue ----
#pragma unroll
    for (int i = 0; i < TM; i++) {
        int gm = m0 + trow * TM + i;
#pragma unroll
        for (int j = 0; j < TN; j++) {
            int gn = n0 + tcol * TN + j;
            float v = acc[i][j];
            if constexpr (EPI == 0) {
                if (bias) v += bias[gn];
                C[(size_t)gm * N + gn] = v;
            } else if constexpr (EPI == 1) {
                v += bias[gn];
                C[(size_t)gm * N + gn] = fmaxf(v, 0.0f);
            } else if constexpr (EPI == 2) {
                float gt = 1.0f / (1.0f + expf(-gate[0]));
                if (gn < 128) {
                    v += bias[gn];
                    float sn, cs; sincosf(v, &sn, &cs);
                    C[(size_t)gm * 1024 + gn]       = gt * cs;
                    C[(size_t)gm * 1024 + 128 + gn] = gt * sn;
                } else {
                    v += bias2[gn - 128];
                    float ge = 0.5f * v * (1.0f + erff(v * 0.70710678118654752f));
                    C[(size_t)gm * 1024 + 128 + gn] = (1.0f - gt) * ge;
                }
            } else { // EPI == 3
                v += bias[gn];
                C[(((size_t)(gm >> 6)) * 512 + gn) * 64 + (gm & 63)] = v;
            }
        }
    }
}

// ---------------- top-k frequency filter + irfft reconstruction ----------------
__global__ __launch_bounds__(256) void filter_kernel(
    const float* __restrict__ x, float* __restrict__ xfilt, float* __restrict__ xnorm)
{
    __shared__ float xs[LSEQ];
    __shared__ float mg[NFREQ + 3];
    __shared__ float twc[LSEQ], tws[LSEQ];
    __shared__ float rmax[256];
    __shared__ int   rid[256];
    __shared__ int   selF[KTOP];
    __shared__ float selR[KTOP], selI[KTOP];

    const int tid = threadIdx.x;
    const int m = blockIdx.x;
    const int b = m >> 6, c = m & 63;
    const float* sp = g_spec + (size_t)m * NSPEC;

    for (int j = tid; j < LSEQ; j += 256) {
        twc[j] = g_tw[2 * j];
        tws[j] = g_tw[2 * j + 1];
        xs[j]  = x[((size_t)b * LSEQ + j) * NE + c];
    }
    for (int f = tid; f < NFREQ; f += 256) {
        float re = sp[2 * f], im = sp[2 * f + 1];
        mg[f] = re * re + im * im;
    }
    __syncthreads();

    for (int it = 0; it < KTOP; it++) {
        float best = -1.0f; int bi = 0;
        for (int f = tid; f < NFREQ; f += 256) {
            float v = mg[f];
            if (v > best) { best = v; bi = f; }
        }
        rmax[tid] = best; rid[tid] = bi;
        __syncthreads();
        for (int s = 128; s > 0; s >>= 1) {
            if (tid < s) {
                float o = rmax[tid + s];
                if (o > rmax[tid] || (o == rmax[tid] && rid[tid + s] < rid[tid])) {
                    rmax[tid] = o; rid[tid] = rid[tid + s];
                }
            }
            __syncthreads();
        }
        if (tid == 0) {
            int f = rid[0];
            selF[it] = f;
            mg[f] = -2.0f;
            float w = (f == 0 || f == 256) ? 1.0f : 2.0f;
            float sc = w * (1.0f / 512.0f);
            selR[it] = sp[2 * f] * sc;
            selI[it] = sp[2 * f + 1] * sc;
        }
        __syncthreads();
    }

    for (int t = tid; t < LSEQ; t += 256) {
        float s = 0.0f;
#pragma unroll
        for (int i = 0; i < KTOP; i++) {
            int j = (selF[i] * t) & 511;
            s += selR[i] * twc[j] - selI[i] * tws[j];
        }
        size_t o = ((size_t)b * LSEQ + t) * NE + c;
        xfilt[o] = s;
        xnorm[o] = xs[t] - s;
    }
}

// ---------------- fused attention (per (batch, 64 q rows)): S, softmax, PV, out-proj ----------------
__global__ __launch_bounds__(256) void attn_kernel(
    const float* __restrict__ Q, const float* __restrict__ Km, const float* __restrict__ V,
    const float* __restrict__ Wo, const float* __restrict__ bo, float* __restrict__ out)
{
    extern __shared__ float sm[];
    float* sQ = sm;           // [64 e][65] : sQ[e*65 + q]
    float* sT = sm + 4160;    // K/V/W tile
    float* sS = sm + 8320;    // [64 q][520]

    const int tid = threadIdx.x;
    const int b  = blockIdx.y;
    const int q0 = blockIdx.x * 64;
    const float* Qb = Q + ((size_t)b * LSEQ + q0) * NE;
    const float* Kb = Km + (size_t)b * LSEQ * NE;
    const float* Vb = V + (size_t)b * LSEQ * NE;
    const int tcol = tid & 15;
    const int trow = tid >> 4;

    // load Q transposed: sQ[e][q]
    for (int i = tid; i < 4096; i += 256) {
        int e = i & 63, r = i >> 6;
        sQ[e * 65 + r] = Qb[r * 64 + e];
    }

    // phase 1: S = Q K^T / 8
    for (int kt = 0; kt < 8; kt++) {
        __syncthreads();
        for (int i = tid; i < 4096; i += 256) {
            int e = i & 63, kc = i >> 6;
            sT[e * 65 + kc] = Kb[(kt * 64 + kc) * 64 + e];
        }
        __syncthreads();
        float acc[4][4] = {};
#pragma unroll 8
        for (int e = 0; e < 64; e++) {
            float a[4], bb[4];
#pragma unroll
            for (int i = 0; i < 4; i++) a[i]  = sQ[e * 65 + trow * 4 + i];
#pragma unroll
            for (int j = 0; j < 4; j++) bb[j] = sT[e * 65 + tcol * 4 + j];
#pragma unroll
            for (int i = 0; i < 4; i++)
#pragma unroll
                for (int j = 0; j < 4; j++) acc[i][j] = fmaf(a[i], bb[j], acc[i][j]);
        }
#pragma unroll
        for (int i = 0; i < 4; i++)
#pragma unroll
            for (int j = 0; j < 4; j++)
                sS[(trow * 4 + i) * 520 + kt * 64 + tcol * 4 + j] = acc[i][j] * 0.125f;
    }
    __syncthreads();

    // phase 2: softmax (warp per row)
    {
        int warp = tid >> 5, lane = tid & 31;
        for (int rr = 0; rr < 8; rr++) {
            int r = warp * 8 + rr;
            float vals[16];
            float mx = -1e30f;
#pragma unroll
            for (int j = 0; j < 16; j++) { vals[j] = sS[r * 520 + j * 32 + lane]; mx = fmaxf(mx, vals[j]); }
#pragma unroll
            for (int o = 16; o > 0; o >>= 1) mx = fmaxf(mx, __shfl_xor_sync(0xffffffffu, mx, o));
            float sum = 0.0f;
#pragma unroll
            for (int j = 0; j < 16; j++) { vals[j] = __expf(vals[j] - mx); sum += vals[j]; }
#pragma unroll
            for (int o = 16; o > 0; o >>= 1) sum += __shfl_xor_sync(0xffffffffu, sum, o);
            float inv = 1.0f / sum;
#pragma unroll
            for (int j = 0; j < 16; j++) sS[r * 520 + j * 32 + lane] = vals[j] * inv;
        }
    }
    __syncthreads();

    // phase 3: O = P V
    float oacc[4][4] = {};
    for (int vt = 0; vt < 8; vt++) {
        for (int i = tid; i < 4096; i += 256) {
            int e = i & 63, kk = i >> 6;
            sT[kk * 65 + e] = Vb[(vt * 64 + kk) * 64 + e];
        }
        __syncthreads();
#pragma unroll 8
        for (int kk = 0; kk < 64; kk++) {
            float p[4], bb[4];
#pragma unroll
            for (int i = 0; i < 4; i++) p[i]  = sS[(trow * 4 + i) * 520 + vt * 64 + kk];
#pragma unroll
            for (int j = 0; j < 4; j++) bb[j] = sT[kk * 65 + tcol * 4 + j];
#pragma unroll
            for (int i = 0; i < 4; i++)
#pragma unroll
                for (int j = 0; j < 4; j++) oacc[i][j] = fmaf(p[i], bb[j], oacc[i][j]);
        }
        __syncthreads();
    }

    // phase 4: out projection  final = O @ Wo^T + bo
#pragma unroll
    for (int i = 0; i < 4; i++)
#pragma unroll
        for (int j = 0; j < 4; j++)
            sQ[(tcol * 4 + j) * 65 + (trow * 4 + i)] = oacc[i][j];  // sO[e][q]
    for (int i = tid; i < 4096; i += 256) {
        int e = i & 63, n = i >> 6;
        sT[e * 65 + n] = Wo[n * 64 + e];
    }
    __syncthreads();
    float facc[4][4] = {};
#pragma unroll 8
    for (int e = 0; e < 64; e++) {
        float a[4], bb[4];
#pragma unroll
        for (int i = 0; i < 4; i++) a[i]  = sQ[e * 65 + trow * 4 + i];
#pragma unroll
        for (int j = 0; j < 4; j++) bb[j] = sT[e * 65 + tcol * 4 + j];
#pragma unroll
        for (int i = 0; i < 4; i++)
#pragma unroll
            for (int j = 0; j < 4; j++) facc[i][j] = fmaf(a[i], bb[j], facc[i][j]);
    }
#pragma unroll
    for (int i = 0; i < 4; i++)
#pragma unroll
        for (int j = 0; j < 4; j++)
            out[((size_t)b * LSEQ + q0 + trow * 4 + i) * NE + tcol * 4 + j] = facc[i][j] + bo[tcol * 4 + j];
}

// ---------------- xt copy: h[m][512+t] = batch_x[b][t][c] (smem transpose) ----------------
__global__ __launch_bounds__(256) void xt_kernel(const float* __restrict__ x, float* __restrict__ h)
{
    __shared__ float s[64 * 65];
    const int b = blockIdx.y, t0 = blockIdx.x * 64;
    const int tid = threadIdx.x;
    for (int i = tid; i < 4096; i += 256) {
        int cc = i & 63, tt = i >> 6;
        s[tt * 65 + cc] = x[((size_t)b * LSEQ + t0 + tt) * NE + cc];
    }
    __syncthreads();
    for (int i = tid; i < 4096; i += 256) {
        int t = i & 63, cidx = i >> 6;
        h[((size_t)b * 64 + cidx) * 1024 + 512 + t0 + t] = s[t * 65 + cidx];
    }
}

// ---------------- launch ----------------
extern "C" void kernel_launch(void* const* d_in, const int* in_sizes, int n_in,
                              void* d_out, int out_size)
{
    const float* batch_x   = (const float*)d_in[0];
    const float* in_proj_w = (const float*)d_in[1];
    const float* in_proj_b = (const float*)d_in[2];
    const float* out_w     = (const float*)d_in[3];
    const float* out_b     = (const float*)d_in[4];
    const float* Wp        = (const float*)d_in[5];
    const float* bp        = (const float*)d_in[6];
    const float* Wg        = (const float*)d_in[7];
    const float* bg        = (const float*)d_in[8];
    const float* gate      = (const float*)d_in[9];
    const float* fc1_w     = (const float*)d_in[10];
    const float* fc1_b     = (const float*)d_in[11];
    const float* fc2_w     = (const float*)d_in[12];
    const float* fc2_b     = (const float*)d_in[13];
    float* out = (float*)d_out;

    float *p_dft, *p_spec, *p_xf, *p_nm, *p_q, *p_k, *p_v, *p_h, *p_hid;
    cudaGetSymbolAddress((void**)&p_dft,  g_dftW);
    cudaGetSymbolAddress((void**)&p_spec, g_spec);
    cudaGetSymbolAddress((void**)&p_xf,   g_xfilt);
    cudaGetSymbolAddress((void**)&p_nm,   g_norm);
    cudaGetSymbolAddress((void**)&p_q,    g_q);
    cudaGetSymbolAddress((void**)&p_k,    g_k);
    cudaGetSymbolAddress((void**)&p_v,    g_v);
    cudaGetSymbolAddress((void**)&p_h,    g_h);
    cudaGetSymbolAddress((void**)&p_hid,  g_hidden);

    // 1) tables
    {
        int tot = NSPEC * LSEQ + LSEQ;
        setup_kernel<<<(tot + 255) / 256, 256>>>();
    }
    // 2) rfft as GEMM: spec = X_t @ Wdft^T    [4096,576] = [4096,512] @ [576,512]^T
    sgemm_kernel<64, 64, 16, 4, 4, 1, 0><<<dim3(9, 64), 256>>>(
        batch_x, p_dft, nullptr, nullptr, nullptr, p_spec, 4096, NSPEC, 512, nullptr);
    // 3) top-k filter + reconstruction
    filter_kernel<<<4096, 256>>>(batch_x, p_xf, p_nm);
    // 4) Q/K/V projections
    sgemm_kernel<64, 64, 16, 4, 4, 0, 0><<<dim3(1, 512), 256>>>(
        p_xf, in_proj_w,        nullptr, in_proj_b,       nullptr, p_q, 32768, 64, 64, nullptr);
    sgemm_kernel<64, 64, 16, 4, 4, 0, 0><<<dim3(1, 512), 256>>>(
        p_nm, in_proj_w + 4096, nullptr, in_proj_b + 64,  nullptr, p_k, 32768, 64, 64, nullptr);
    sgemm_kernel<64, 64, 16, 4, 4, 0, 0><<<dim3(1, 512), 256>>>(
        p_nm, in_proj_w + 8192, nullptr, in_proj_b + 128, nullptr, p_v, 32768, 64, 64, nullptr);
    // 5) fused attention + out projection -> out[0]
    cudaFuncSetAttribute((const void*)attn_kernel,
                         cudaFuncAttributeMaxDynamicSharedMemorySize, 166400);
    attn_kernel<<<dim3(8, 64), 256, 166400>>>(p_q, p_k, p_v, out_w, out_b, out);
    // 6) FAN layer -> h[:, 0:512]
    sgemm_kernel<64, 64, 16, 4, 4, 1, 2><<<dim3(6, 64), 256>>>(
        p_xf, Wp, Wg, bp, bg, p_h, 4096, 384, 512, gate);
    // 7) xt copy -> h[:, 512:1024]
    xt_kernel<<<dim3(8, 64), 256>>>(batch_x, p_h);
    // 8) fc1 + relu
    sgemm_kernel<128, 128, 16, 8, 8, 0, 1><<<dim3(24, 32), 256>>>(
        p_h, fc1_w, nullptr, fc1_b, nullptr, p_hid, 4096, 3072, 1024, nullptr);
    // 9) fc2 + transpose-scatter -> out[1]
    sgemm_kernel<64, 128, 16, 4, 8, 0, 3><<<dim3(4, 64), 256>>>(
        p_hid, fc2_w, nullptr, fc2_b, nullptr, out + 2097152, 4096, 512, 3072, nullptr);
}

// round 11
// speedup vs baseline: 1.5710x; 1.5710x over previous
#include <cuda_runtime.h>
#include <cuda_bf16.h>
#include <math.h>
#include <stdint.h>

// Problem constants
#define NB   64     // batch
#define LSEQ 512    // seq len
#define NE   64     // enc_in
#define NPRED 512
#define KTOP 20
#define NFREQ 257   // rfft bins
#define NSPEC 576   // padded 2*257=514 -> 576 (9 tiles of 64)

// ---------------- scratch (static device memory; no allocations) ----------------
__device__ __align__(16) float g_dftW[NSPEC * LSEQ];
__device__ __align__(16) float g_tw[LSEQ * 2];
__device__ __align__(16) float g_spec[NB * NE * NSPEC];
__device__ __align__(16) float g_xfilt[NB * LSEQ * NE];
__device__ __align__(16) float g_norm [NB * LSEQ * NE];
__device__ __align__(16) float g_q[NB * LSEQ * NE];
__device__ __align__(16) float g_k[NB * LSEQ * NE];
__device__ __align__(16) float g_v[NB * LSEQ * NE];
__device__ __align__(16) float g_h[NB * NE * 1024];           // [4096][1024] MLP input (fp32)

// bf16 split operands for tensor-core GEMMs
__device__ __align__(16) __nv_bfloat16 g_h_hi[4096 * 1024];
__device__ __align__(16) __nv_bfloat16 g_h_lo[4096 * 1024];
__device__ __align__(16) __nv_bfloat16 g_w1_hi[3072 * 1024];
__device__ __align__(16) __nv_bfloat16 g_w1_lo[3072 * 1024];
__device__ __align__(16) __nv_bfloat16 g_hid_hi[4096 * 3072];
__device__ __align__(16) __nv_bfloat16 g_hid_lo[4096 * 3072];
__device__ __align__(16) __nv_bfloat16 g_w2_hi[512 * 3072];
__device__ __align__(16) __nv_bfloat16 g_w2_lo[512 * 3072];

// ================= low-level helpers (cp.async / ldmatrix / mma — all sm_80 PTX) ======
__device__ __forceinline__ uint32_t s2u(const void* p) {
    return (uint32_t)__cvta_generic_to_shared(p);
}
__device__ __forceinline__ void cp16(uint32_t s, const void* g) {
    asm volatile("cp.async.cg.shared.global [%0], [%1], 16;" :: "r"(s), "l"(g));
}
__device__ __forceinline__ void cp_commit() { asm volatile("cp.async.commit_group;" ::: "memory"); }
__device__ __forceinline__ void cp_wait1()  { asm volatile("cp.async.wait_group 1;"  ::: "memory"); }

// XOR swizzle of 16B chunks within a 128-row x 64B tile (conflict-free for
// ldmatrix groups of 8 consecutive rows; verified: banks all distinct)
__device__ __forceinline__ uint32_t sw(uint32_t off) { return off ^ ((off >> 3) & 0x70); }

__device__ __forceinline__ void ldm4(uint32_t* r, uint32_t addr) {
    asm volatile("ldmatrix.sync.aligned.m8n8.x4.shared.b16 {%0,%1,%2,%3}, [%4];"
                 : "=r"(r[0]), "=r"(r[1]), "=r"(r[2]), "=r"(r[3]) : "r"(addr));
}
__device__ __forceinline__ void mma16816(float* c, const uint32_t* a, const uint32_t* b) {
    asm volatile(
        "mma.sync.aligned.m16n8k16.row.col.f32.bf16.bf16.f32 "
        "{%0,%1,%2,%3}, {%4,%5,%6,%7}, {%8,%9}, {%0,%1,%2,%3};"
        : "+f"(c[0]), "+f"(c[1]), "+f"(c[2]), "+f"(c[3])
        : "r"(a[0]), "r"(a[1]), "r"(a[2]), "r"(a[3]), "r"(b[0]), "r"(b[1]));
}

// ================= tensor-core split-bf16 GEMM: C = A @ B^T =================
// Computes Ah*Bh + Ah*Bl + Al*Bh with fp32 accumulation (3 K-passes).
// Block 128x128, 8 warps, warp tile 32(M) x 64(N), K-stage 32, double-buffered.
// EPI 0: v=relu(acc+bias) -> split to bf16 Chi/Clo [M][N]
// EPI 1: v=acc+bias       -> Cf[((m>>6)*512 + n)*64 + (m&63)]  (fc2 transpose-scatter)
template<int EPI>
__global__ __launch_bounds__(256) void mma_gemm_kernel(
    const __nv_bfloat16* __restrict__ Ahi, const __nv_bfloat16* __restrict__ Alo,
    const __nv_bfloat16* __restrict__ Bhi, const __nv_bfloat16* __restrict__ Blo,
    const float* __restrict__ bias,
    __nv_bfloat16* __restrict__ Chi, __nv_bfloat16* __restrict__ Clo,
    float* __restrict__ Cf,
    int N, int K)
{
    __shared__ __align__(1024) __nv_bfloat16 sA[2][128 * 32];
    __shared__ __align__(1024) __nv_bfloat16 sB[2][128 * 32];

    const int tid    = threadIdx.x;
    const int lane   = tid & 31;
    const int wid    = tid >> 5;
    const int warp_m = wid & 3;      // 4 warps over M (32 rows each)
    const int warp_n = wid >> 2;     // 2 warps over N (64 cols each)
    const int m0 = blockIdx.y * 128;
    const int n0 = blockIdx.x * 128;

    float acc[2][8][4];
#pragma unroll
    for (int i = 0; i < 2; i++)
#pragma unroll
        for (int j = 0; j < 8; j++)
#pragma unroll
            for (int x = 0; x < 4; x++) acc[i][j][x] = 0.0f;

    const int KS = K >> 5;           // 32-K stages per pass
    const int S  = 3 * KS;

    // chunk loader: 512 16B-chunks per tile, 2 per thread per matrix
    auto load_stage = [&](int s, int buf) {
        const int pass = s / KS;
        const int k0 = (s - pass * KS) << 5;
        const __nv_bfloat16* Ap = (pass < 2 ? Ahi : Alo) + (size_t)m0 * K + k0;
        const __nv_bfloat16* Bp = (pass == 1 ? Blo : Bhi) + (size_t)n0 * K + k0;
        uint32_t sa = s2u(&sA[buf][0]);
        uint32_t sb = s2u(&sB[buf][0]);
#pragma unroll
        for (int i = 0; i < 2; i++) {
            int q = tid + i * 256;
            int r = q >> 2, c = q & 3;
            uint32_t so = sw(r * 64 + c * 16);
            cp16(sa + so, (const void*)(Ap + (size_t)r * K + c * 8));
            cp16(sb + so, (const void*)(Bp + (size_t)r * K + c * 8));
        }
    };

    load_stage(0, 0);
    cp_commit();

    const int lq = lane >> 3, lr = lane & 7;      // ldmatrix address decomposition

    for (int s = 0; s < S; s++) {
        const int buf = s & 1;
        if (s + 1 < S) load_stage(s + 1, buf ^ 1);
        cp_commit();
        cp_wait1();                  // stage s resident
        __syncthreads();

        uint32_t baseA = s2u(&sA[buf][0]);
        uint32_t baseB = s2u(&sB[buf][0]);
#pragma unroll
        for (int ks = 0; ks < 2; ks++) {
            uint32_t a[2][4];
#pragma unroll
            for (int ma = 0; ma < 2; ma++) {
                int row = warp_m * 32 + ma * 16 + (lq & 1) * 8 + lr;
                ldm4(a[ma], baseA + sw(row * 64 + ks * 32 + (lq >> 1) * 16));
            }
            uint32_t b[8][2];
#pragma unroll
            for (int nb = 0; nb < 4; nb++) {
                int row = warp_n * 64 + nb * 16 + (lq & 1) * 8 + lr;
                uint32_t r4[4];
                ldm4(r4, baseB + sw(row * 64 + ks * 32 + (lq >> 1) * 16));
                b[nb * 2 + 0][0] = r4[0]; b[nb * 2 + 0][1] = r4[2];
                b[nb * 2 + 1][0] = r4[1]; b[nb * 2 + 1][1] = r4[3];
            }
#pragma unroll
            for (int ma = 0; ma < 2; ma++)
#pragma unroll
                for (int na = 0; na < 8; na++)
                    mma16816(acc[ma][na], a[ma], b[na]);
        }
        __syncthreads();
    }

    // ---- epilogue ----
    const int g = lane >> 2, t = lane & 3;
#pragma unroll
    for (int ma = 0; ma < 2; ma++) {
#pragma unroll
        for (int na = 0; na < 8; na++) {
            int m = m0 + warp_m * 32 + ma * 16 + g;
            int n = n0 + warp_n * 64 + na * 8 + 2 * t;
            float b0 = bias[n], b1 = bias[n + 1];
            float v0 = acc[ma][na][0] + b0;
            float v1 = acc[ma][na][1] + b1;
            float v2 = acc[ma][na][2] + b0;
            float v3 = acc[ma][na][3] + b1;
            if constexpr (EPI == 0) {
                v0 = fmaxf(v0, 0.0f); v1 = fmaxf(v1, 0.0f);
                v2 = fmaxf(v2, 0.0f); v3 = fmaxf(v3, 0.0f);
                __nv_bfloat16 h0 = __float2bfloat16(v0), h1 = __float2bfloat16(v1);
                __nv_bfloat16 h2 = __float2bfloat16(v2), h3 = __float2bfloat16(v3);
                size_t o0 = (size_t)m * N + n;
                size_t o2 = (size_t)(m + 8) * N + n;
                *reinterpret_cast<__nv_bfloat162*>(&Chi[o0]) = __nv_bfloat162(h0, h1);
                *reinterpret_cast<__nv_bfloat162*>(&Chi[o2]) = __nv_bfloat162(h2, h3);
                *reinterpret_cast<__nv_bfloat162*>(&Clo[o0]) =
                    __nv_bfloat162(__float2bfloat16(v0 - __bfloat162float(h0)),
                                   __float2bfloat16(v1 - __bfloat162float(h1)));
                *reinterpret_cast<__nv_bfloat162*>(&Clo[o2]) =
                    __nv_bfloat162(__float2bfloat16(v2 - __bfloat162float(h2)),
                                   __float2bfloat16(v3 - __bfloat162float(h3)));
            } else {
                int m2 = m + 8;
                Cf[(((size_t)(m  >> 6)) * 512 + n)     * 64 + (m  & 63)] = v0;
                Cf[(((size_t)(m  >> 6)) * 512 + n + 1) * 64 + (m  & 63)] = v1;
                Cf[(((size_t)(m2 >> 6)) * 512 + n)     * 64 + (m2 & 63)] = v2;
                Cf[(((size_t)(m2 >> 6)) * 512 + n + 1) * 64 + (m2 & 63)] = v3;
            }
        }
    }
}

// ---------------- fp32 -> bf16 hi/lo split ----------------
__global__ __launch_bounds__(256) void split_kernel(
    const float* __restrict__ src, __nv_bfloat16* __restrict__ hi,
    __nv_bfloat16* __restrict__ lo, int n4)
{
    int i = blockIdx.x * blockDim.x + threadIdx.x;
    if (i < n4) {
        float4 v = reinterpret_cast<const float4*>(src)[i];
        __nv_bfloat16 h0 = __float2bfloat16(v.x), h1 = __float2bfloat16(v.y);
        __nv_bfloat16 h2 = __float2bfloat16(v.z), h3 = __float2bfloat16(v.w);
        __nv_bfloat162* H = reinterpret_cast<__nv_bfloat162*>(hi);
        __nv_bfloat162* L = reinterpret_cast<__nv_bfloat162*>(lo);
        H[2 * i]     = __nv_bfloat162(h0, h1);
        H[2 * i + 1] = __nv_bfloat162(h2, h3);
        L[2 * i]     = __nv_bfloat162(__float2bfloat16(v.x - __bfloat162float(h0)),
                                      __float2bfloat16(v.y - __bfloat162float(h1)));
        L[2 * i + 1] = __nv_bfloat162(__float2bfloat16(v.z - __bfloat162float(h2)),
                                      __float2bfloat16(v.w - __bfloat162float(h3)));
    }
}

// ---------------- setup: DFT matrix + twiddle table ----------------
__global__ void setup_kernel() {
    int i = blockIdx.x * blockDim.x + threadIdx.x;
    const float w0 = 6.283185307179586f / 512.0f;
    if (i < NSPEC * LSEQ) {
        int n = i / LSEQ, t = i % LSEQ;
        float v = 0.0f;
        if (n < 2 * NFREQ) {
            int f = n >> 1;
            int j = (f * t) & 511;
            float ang = (float)j * w0;
            v = (n & 1) ? -sinf(ang) : cosf(ang);
        }
        g_dftW[i] = v;
    } else if (i < NSPEC * LSEQ + LSEQ) {
        int j = i - NSPEC * LSEQ;
        float ang = (float)j * w0;
        float s, c; sincosf(ang, &s, &c);
        g_tw[2 * j] = c; g_tw[2 * j + 1] = s;
    }
}

// ---------------- generic register-tiled SGEMM: C = A @ B^T (+bias, epilogue) ----------------
template<int BM, int BN, int BK, int TM, int TN, int AMODE, int EPI>
__global__ __launch_bounds__(256) void sgemm_kernel(
    const float* __restrict__ A, const float* __restrict__ B,
    const float* __restrict__ B2, const float* __restrict__ bias,
    const float* __restrict__ bias2, float* __restrict__ C,
    int M, int N, int K, const float* __restrict__ gate)
{
    constexpr int LDA = BM + 4;
    constexpr int LDB = BN + 4;
    static_assert((BM / TM) * (BN / TN) == 256, "thread count");
    __shared__ __align__(16) float As[BK * LDA];
    __shared__ __align__(16) float Bs[BK * LDB];

    const int tid  = threadIdx.x;
    const int m0   = blockIdx.y * BM;
    const int n0   = blockIdx.x * BN;
    const int tcol = tid & ((BN / TN) - 1);
    const int trow = tid / (BN / TN);

    float acc[TM][TN];
#pragma unroll
    for (int i = 0; i < TM; i++)
#pragma unroll
        for (int j = 0; j < TN; j++) acc[i][j] = 0.0f;

    for (int k0 = 0; k0 < K; k0 += BK) {
        if constexpr (AMODE == 0) {
#pragma unroll
            for (int i = tid * 4; i < BM * BK; i += 1024) {
                int row = i / BK, col = i % BK;
                float4 va = *reinterpret_cast<const float4*>(&A[(size_t)(m0 + row) * K + k0 + col]);
                As[(col + 0) * LDA + row] = va.x;
                As[(col + 1) * LDA + row] = va.y;
                As[(col + 2) * LDA + row] = va.z;
                As[(col + 3) * LDA + row] = va.w;
            }
        } else {
#pragma unroll
            for (int i = tid; i < BM * BK; i += 256) {
                int row = i & (BM - 1);
                int col = i / BM;
                int gm = m0 + row;
                As[col * LDA + row] = A[((size_t)(gm >> 6) * K + (k0 + col)) * 64 + (gm & 63)];
            }
        }
#pragma unroll
        for (int i = tid * 4; i < BN * BK; i += 1024) {
            int row = i / BK, col = i % BK;
            int gn = n0 + row;
            const float* Bp;
            if constexpr (EPI == 2) Bp = (gn < 128) ? (B + (size_t)gn * K) : (B2 + (size_t)(gn - 128) * K);
            else                    Bp = B + (size_t)gn * K;
            float4 vb = *reinterpret_cast<const float4*>(&Bp[k0 + col]);
            Bs[(col + 0) * LDB + row] = vb.x;
            Bs[(col + 1) * LDB + row] = vb.y;
            Bs[(col + 2) * LDB + row] = vb.z;
            Bs[(col + 3) * LDB + row] = vb.w;
        }
        __syncthreads();
#pragma unroll
        for (int k = 0; k < BK; k++) {
            float a[TM], bv[TN];
#pragma unroll
            for (int i = 0; i < TM; i += 4)
                *reinterpret_cast<float4*>(&a[i]) =
                    *reinterpret_cast<const float4*>(&As[k * LDA + trow * TM + i]);
#pragma unroll
            for (int j = 0; j < TN; j += 4)
                *reinterpret_cast<float4*>(&bv[j]) =
                    *reinterpret_cast<const float4*>(&Bs[k * LDB + tcol * TN + j]);
#pragma unroll
            for (int i = 0; i < TM; i++)
#pragma unroll
                for (int j = 0; j < TN; j++)
                    acc[i][j] = fmaf(a[i], bv[j], acc[i][j]);
        }
        __syncthreads();
    }

#pragma unroll
    for (int i = 0; i < TM; i++) {
        int gm = m0 + trow * TM + i;
#pragma unroll
        for (int j = 0; j < TN; j++) {
            int gn = n0 + tcol * TN + j;
            float v = acc[i][j];
            if constexpr (EPI == 0) {
                if (bias) v += bias[gn];
                C[(size_t)gm * N + gn] = v;
            } else if constexpr (EPI == 1) {
                v += bias[gn];
                C[(size_t)gm * N + gn] = fmaxf(v, 0.0f);
            } else if constexpr (EPI == 2) {
                float gt = 1.0f / (1.0f + expf(-gate[0]));
                if (gn < 128) {
                    v += bias[gn];
                    float sn, cs; sincosf(v, &sn, &cs);
                    C[(size_t)gm * 1024 + gn]       = gt * cs;
                    C[(size_t)gm * 1024 + 128 + gn] = gt * sn;
                } else {
                    v += bias2[gn - 128];
                    float ge = 0.5f * v * (1.0f + erff(v * 0.70710678118654752f));
                    C[(size_t)gm * 1024 + 128 + gn] = (1.0f - gt) * ge;
                }
            } else { // EPI == 3
                v += bias[gn];
                C[(((size_t)(gm >> 6)) * 512 + gn) * 64 + (gm & 63)] = v;
            }
        }
    }
}

// ---------------- top-k frequency filter + irfft reconstruction ----------------
__global__ __launch_bounds__(256) void filter_kernel(
    const float* __restrict__ x, float* __restrict__ xfilt, float* __restrict__ xnorm)
{
    __shared__ float xs[LSEQ];
    __shared__ float mg[NFREQ + 3];
    __shared__ float twc[LSEQ], tws[LSEQ];
    __shared__ float rmax[256];
    __shared__ int   rid[256];
    __shared__ int   selF[KTOP];
    __shared__ float selR[KTOP], selI[KTOP];

    const int tid = threadIdx.x;
    const int m = blockIdx.x;
    const int b = m >> 6, c = m & 63;
    const float* sp = g_spec + (size_t)m * NSPEC;

    for (int j = tid; j < LSEQ; j += 256) {
        twc[j] = g_tw[2 * j];
        tws[j] = g_tw[2 * j + 1];
        xs[j]  = x[((size_t)b * LSEQ + j) * NE + c];
    }
    for (int f = tid; f < NFREQ; f += 256) {
        float re = sp[2 * f], im = sp[2 * f + 1];
        mg[f] = re * re + im * im;
    }
    __syncthreads();

    for (int it = 0; it < KTOP; it++) {
        float best = -1.0f; int bi = 0;
        for (int f = tid; f < NFREQ; f += 256) {
            float v = mg[f];
            if (v > best) { best = v; bi = f; }
        }
        rmax[tid] = best; rid[tid] = bi;
        __syncthreads();
        for (int s = 128; s > 0; s >>= 1) {
            if (tid < s) {
                float o = rmax[tid + s];
                if (o > rmax[tid] || (o == rmax[tid] && rid[tid + s] < rid[tid])) {
                    rmax[tid] = o; rid[tid] = rid[tid + s];
                }
            }
            __syncthreads();
        }
        if (tid == 0) {
            int f = rid[0];
            selF[it] = f;
            mg[f] = -2.0f;
            float w = (f == 0 || f == 256) ? 1.0f : 2.0f;
            float sc = w * (1.0f / 512.0f);
            selR[it] = sp[2 * f] * sc;
            selI[it] = sp[2 * f + 1] * sc;
        }
        __syncthreads();
    }

    for (int t = tid; t < LSEQ; t += 256) {
        float s = 0.0f;
#pragma unroll
        for (int i = 0; i < KTOP; i++) {
            int j = (selF[i] * t) & 511;
            s += selR[i] * twc[j] - selI[i] * tws[j];
        }
        size_t o = ((size_t)b * LSEQ + t) * NE + c;
        xfilt[o] = s;
        xnorm[o] = xs[t] - s;
    }
}

// ---------------- fused attention (per (batch, 64 q rows)) ----------------
__global__ __launch_bounds__(256) void attn_kernel(
    const float* __restrict__ Q, const float* __restrict__ Km, const float* __restrict__ V,
    const float* __restrict__ Wo, const float* __restrict__ bo, float* __restrict__ out)
{
    extern __shared__ float sm[];
    float* sQ = sm;           // [64 e][65]
    float* sT = sm + 4160;
    float* sS = sm + 8320;    // [64 q][520]

    const int tid = threadIdx.x;
    const int b  = blockIdx.y;
    const int q0 = blockIdx.x * 64;
    const float* Qb = Q + ((size_t)b * LSEQ + q0) * NE;
    const float* Kb = Km + (size_t)b * LSEQ * NE;
    const float* Vb = V + (size_t)b * LSEQ * NE;
    const int tcol = tid & 15;
    const int trow = tid >> 4;

    for (int i = tid; i < 4096; i += 256) {
        int e = i & 63, r = i >> 6;
        sQ[e * 65 + r] = Qb[r * 64 + e];
    }

    for (int kt = 0; kt < 8; kt++) {
        __syncthreads();
        for (int i = tid; i < 4096; i += 256) {
            int e = i & 63, kc = i >> 6;
            sT[e * 65 + kc] = Kb[(kt * 64 + kc) * 64 + e];
        }
        __syncthreads();
        float acc[4][4] = {};
#pragma unroll 8
        for (int e = 0; e < 64; e++) {
            float a[4], bb[4];
#pragma unroll
            for (int i = 0; i < 4; i++) a[i]  = sQ[e * 65 + trow * 4 + i];
#pragma unroll
            for (int j = 0; j < 4; j++) bb[j] = sT[e * 65 + tcol * 4 + j];
#pragma unroll
            for (int i = 0; i < 4; i++)
#pragma unroll
                for (int j = 0; j < 4; j++) acc[i][j] = fmaf(a[i], bb[j], acc[i][j]);
        }
#pragma unroll
        for (int i = 0; i < 4; i++)
#pragma unroll
            for (int j = 0; j < 4; j++)
                sS[(trow * 4 + i) * 520 + kt * 64 + tcol * 4 + j] = acc[i][j] * 0.125f;
    }
    __syncthreads();

    {
        int warp = tid >> 5, lane = tid & 31;
        for (int rr = 0; rr < 8; rr++) {
            int r = warp * 8 + rr;
            float vals[16];
            float mx = -1e30f;
#pragma unroll
            for (int j = 0; j < 16; j++) { vals[j] = sS[r * 520 + j * 32 + lane]; mx = fmaxf(mx, vals[j]); }
#pragma unroll
            for (int o = 16; o > 0; o >>= 1) mx = fmaxf(mx, __shfl_xor_sync(0xffffffffu, mx, o));
            float sum = 0.0f;
#pragma unroll
            for (int j = 0; j < 16; j++) { vals[j] = __expf(vals[j] - mx); sum += vals[j]; }
#pragma unroll
            for (int o = 16; o > 0; o >>= 1) sum += __shfl_xor_sync(0xffffffffu, sum, o);
            float inv = 1.0f / sum;
#pragma unroll
            for (int j = 0; j < 16; j++) sS[r * 520 + j * 32 + lane] = vals[j] * inv;
        }
    }
    __syncthreads();

    float oacc[4][4] = {};
    for (int vt = 0; vt < 8; vt++) {
        for (int i = tid; i < 4096; i += 256) {
            int e = i & 63, kk = i >> 6;
            sT[kk * 65 + e] = Vb[(vt * 64 + kk) * 64 + e];
        }
        __syncthreads();
#pragma unroll 8
        for (int kk = 0; kk < 64; kk++) {
            float p[4], bb[4];
#pragma unroll
            for (int i = 0; i < 4; i++) p[i]  = sS[(trow * 4 + i) * 520 + vt * 64 + kk];
#pragma unroll
            for (int j = 0; j < 4; j++) bb[j] = sT[kk * 65 + tcol * 4 + j];
#pragma unroll
            for (int i = 0; i < 4; i++)
#pragma unroll
                for (int j = 0; j < 4; j++) oacc[i][j] = fmaf(p[i], bb[j], oacc[i][j]);
        }
        __syncthreads();
    }

#pragma unroll
    for (int i = 0; i < 4; i++)
#pragma unroll
        for (int j = 0; j < 4; j++)
            sQ[(tcol * 4 + j) * 65 + (trow * 4 + i)] = oacc[i][j];
    for (int i = tid; i < 4096; i += 256) {
        int e = i & 63, n = i >> 6;
        sT[e * 65 + n] = Wo[n * 64 + e];
    }
    __syncthreads();
    float facc[4][4] = {};
#pragma unroll 8
    for (int e = 0; e < 64; e++) {
        float a[4], bb[4];
#pragma unroll
        for (int i = 0; i < 4; i++) a[i]  = sQ[e * 65 + trow * 4 + i];
#pragma unroll
        for (int j = 0; j < 4; j++) bb[j] = sT[e * 65 + tcol * 4 + j];
#pragma unroll
        for (int i = 0; i < 4; i++)
#pragma unroll
            for (int j = 0; j < 4; j++) facc[i][j] = fmaf(a[i], bb[j], facc[i][j]);
    }
#pragma unroll
    for (int i = 0; i < 4; i++)
#pragma unroll
        for (int j = 0; j < 4; j++)
            out[((size_t)b * LSEQ + q0 + trow * 4 + i) * NE + tcol * 4 + j] = facc[i][j] + bo[tcol * 4 + j];
}

// ---------------- xt copy: h[m][512+t] = batch_x[b][t][c] ----------------
__global__ __launch_bounds__(256) void xt_kernel(const float* __restrict__ x, float* __restrict__ h)
{
    __shared__ float s[64 * 65];
    const int b = blockIdx.y, t0 = blockIdx.x * 64;
    const int tid = threadIdx.x;
    for (int i = tid; i < 4096; i += 256) {
        int cc = i & 63, tt = i >> 6;
        s[tt * 65 + cc] = x[((size_t)b * LSEQ + t0 + tt) * NE + cc];
    }
    __syncthreads();
    for (int i = tid; i < 4096; i += 256) {
        int t = i & 63, cidx = i >> 6;
        h[((size_t)b * 64 + cidx) * 1024 + 512 + t0 + t] = s[t * 65 + cidx];
    }
}

// ---------------- launch ----------------
extern "C" void kernel_launch(void* const* d_in, const int* in_sizes, int n_in,
                              void* d_out, int out_size)
{
    const float* batch_x   = (const float*)d_in[0];
    const float* in_proj_w = (const float*)d_in[1];
    const float* in_proj_b = (const float*)d_in[2];
    const float* out_w     = (const float*)d_in[3];
    const float* out_b     = (const float*)d_in[4];
    const float* Wp        = (const float*)d_in[5];
    const float* bp        = (const float*)d_in[6];
    const float* Wg        = (const float*)d_in[7];
    const float* bg        = (const float*)d_in[8];
    const float* gate      = (const float*)d_in[9];
    const float* fc1_w     = (const float*)d_in[10];
    const float* fc1_b     = (const float*)d_in[11];
    const float* fc2_w     = (const float*)d_in[12];
    const float* fc2_b     = (const float*)d_in[13];
    float* out = (float*)d_out;

    float *p_dft, *p_spec, *p_xf, *p_nm, *p_q, *p_k, *p_v, *p_h;
    __nv_bfloat16 *p_hhi, *p_hlo, *p_w1hi, *p_w1lo, *p_hidhi, *p_hidlo, *p_w2hi, *p_w2lo;
    cudaGetSymbolAddress((void**)&p_dft,   g_dftW);
    cudaGetSymbolAddress((void**)&p_spec,  g_spec);
    cudaGetSymbolAddress((void**)&p_xf,    g_xfilt);
    cudaGetSymbolAddress((void**)&p_nm,    g_norm);
    cudaGetSymbolAddress((void**)&p_q,     g_q);
    cudaGetSymbolAddress((void**)&p_k,     g_k);
    cudaGetSymbolAddress((void**)&p_v,     g_v);
    cudaGetSymbolAddress((void**)&p_h,     g_h);
    cudaGetSymbolAddress((void**)&p_hhi,   g_h_hi);
    cudaGetSymbolAddress((void**)&p_hlo,   g_h_lo);
    cudaGetSymbolAddress((void**)&p_w1hi,  g_w1_hi);
    cudaGetSymbolAddress((void**)&p_w1lo,  g_w1_lo);
    cudaGetSymbolAddress((void**)&p_hidhi, g_hid_hi);
    cudaGetSymbolAddress((void**)&p_hidlo, g_hid_lo);
    cudaGetSymbolAddress((void**)&p_w2hi,  g_w2_hi);
    cudaGetSymbolAddress((void**)&p_w2lo,  g_w2_lo);

    // 1) tables
    {
        int tot = NSPEC * LSEQ + LSEQ;
        setup_kernel<<<(tot + 255) / 256, 256>>>();
    }
    // 2) rfft as GEMM
    sgemm_kernel<64, 64, 16, 4, 4, 1, 0><<<dim3(9, 64), 256>>>(
        batch_x, p_dft, nullptr, nullptr, nullptr, p_spec, 4096, NSPEC, 512, nullptr);
    // 3) top-k filter + reconstruction
    filter_kernel<<<4096, 256>>>(batch_x, p_xf, p_nm);
    // 4) Q/K/V projections
    sgemm_kernel<64, 64, 16, 4, 4, 0, 0><<<dim3(1, 512), 256>>>(
        p_xf, in_proj_w,        nullptr, in_proj_b,       nullptr, p_q, 32768, 64, 64, nullptr);
    sgemm_kernel<64, 64, 16, 4, 4, 0, 0><<<dim3(1, 512), 256>>>(
        p_nm, in_proj_w + 4096, nullptr, in_proj_b + 64,  nullptr, p_k, 32768, 64, 64, nullptr);
    sgemm_kernel<64, 64, 16, 4, 4, 0, 0><<<dim3(1, 512), 256>>>(
        p_nm, in_proj_w + 8192, nullptr, in_proj_b + 128, nullptr, p_v, 32768, 64, 64, nullptr);
    // 5) fused attention -> out[0]
    cudaFuncSetAttribute((const void*)attn_kernel,
                         cudaFuncAttributeMaxDynamicSharedMemorySize, 166400);
    attn_kernel<<<dim3(8, 64), 256, 166400>>>(p_q, p_k, p_v, out_w, out_b, out);
    // 6) FAN layer -> h[:, 0:512]
    sgemm_kernel<64, 64, 16, 4, 4, 1, 2><<<dim3(6, 64), 256>>>(
        p_xf, Wp, Wg, bp, bg, p_h, 4096, 384, 512, gate);
    // 7) xt copy -> h[:, 512:1024]
    xt_kernel<<<dim3(8, 64), 256>>>(batch_x, p_h);
    // 8) bf16 splits for tensor-core GEMMs
    split_kernel<<<(1048576 + 255) / 256, 256>>>(p_h,   p_hhi,  p_hlo,  1048576);  // 4096*1024/4
    split_kernel<<<(786432  + 255) / 256, 256>>>(fc1_w, p_w1hi, p_w1lo, 786432);   // 3072*1024/4
    split_kernel<<<(393216  + 255) / 256, 256>>>(fc2_w, p_w2hi, p_w2lo, 393216);   // 512*3072/4
    // 9) fc1 + relu (HMMA split-bf16) -> hid hi/lo
    mma_gemm_kernel<0><<<dim3(24, 32), 256>>>(
        p_hhi, p_hlo, p_w1hi, p_w1lo, fc1_b, p_hidhi, p_hidlo, nullptr, 3072, 1024);
    // 10) fc2 + transpose-scatter (HMMA split-bf16) -> out[1]
    mma_gemm_kernel<1><<<dim3(4, 32), 256>>>(
        p_hidhi, p_hidlo, p_w2hi, p_w2lo, fc2_b, nullptr, nullptr, out + 2097152, 512, 3072);
}